// round 5
// baseline (speedup 1.0000x reference)
#include <cuda_runtime.h>
#include <cuda_fp16.h>

// Grid4D quadrilinear sample, three-phase:
//  1) transpose grid [R,X,Y,U,V] fp32 -> gridT [X,Y,U,V,R] fp16 (16B/cell)
//  2) bin points by (x0,y0,u0>>6) -> 512 bins (device histogram+scan+scatter)
//  3) gather in bin order: concurrent working set fits L2 -> repeat hits cheap

#define RR 8
#define XX 9
#define YY 9
#define UU 512
#define VV 512
#define NS (XX * YY * UU * VV)     // 21,233,664 spatial cells
#define STR_R (NS)

#define NBINS 512
#define NCAP (1 << 20)

__device__ uint4 g_gridT[(size_t)NS];            // ~340 MB fp16 transposed grid
__device__ unsigned int g_binCnt[NBINS];
__device__ unsigned int g_binCursor[NBINS];
__device__ unsigned int g_binIdx[NCAP];          // 4 MB point order

__device__ __forceinline__ unsigned int h2_to_u32(__half2 v) {
    return *reinterpret_cast<unsigned int*>(&v);
}
__device__ __forceinline__ __half2 u32_to_h2(unsigned int v) {
    return *reinterpret_cast<__half2*>(&v);
}

// ---------------- phase 1: transpose ----------------
__global__ void __launch_bounds__(256)
transpose_kernel(const float* __restrict__ grid) {
    int s = blockIdx.x * blockDim.x + threadIdx.x;
    if (s >= NS) return;
    uint4 packed;
    unsigned int* pu = &packed.x;
#pragma unroll
    for (int p = 0; p < 4; p++) {
        float a = __ldg(grid + (2 * p + 0) * STR_R + s);
        float b = __ldg(grid + (2 * p + 1) * STR_R + s);
        pu[p] = h2_to_u32(__floats2half2_rn(a, b));
    }
    g_gridT[s] = packed;
}

// ---------------- shared coordinate math ----------------
__device__ __forceinline__ void prep_dim(float c, float mn, float mx, int S,
                                         int& c0, int& dd, float& w0, float& w1) {
    float ind = (c - mn) / (mx - mn) * 2.0f - 1.0f;
    float pos = (ind + 1.0f) * 0.5f * (float)(S - 1);
    float fl = floorf(pos);
    int i0 = (int)fl;
    float f = pos - fl;
    w0 = 1.0f - f;
    w1 = f;
    if (i0 < 0 || i0 >= S) w0 = 0.0f;        // zero-padding semantics
    int i1 = i0 + 1;
    if (i1 < 0 || i1 >= S) w1 = 0.0f;
    int cc0 = min(max(i0, 0), S - 1);
    int cc1 = min(max(i1, 0), S - 1);
    c0 = cc0;
    dd = cc1 - cc0;                           // 0 or 1
}

__device__ __forceinline__ int base_idx(float c, float mn, float mx, int S) {
    float ind = (c - mn) / (mx - mn) * 2.0f - 1.0f;
    float pos = (ind + 1.0f) * 0.5f * (float)(S - 1);
    int i0 = (int)floorf(pos);
    return min(max(i0, 0), S - 1);
}

__device__ __forceinline__ int compute_bin(float4 c, const float* mn4, const float* mx4) {
    int x0 = base_idx(c.x, mn4[0], mx4[0], XX);
    int y0 = base_idx(c.y, mn4[1], mx4[1], YY);
    int u0 = base_idx(c.z, mn4[2], mx4[2], UU);
    return (min(x0, 7) << 6) | (min(y0, 7) << 3) | (u0 >> 6);
}

// ---------------- phase 2: binning ----------------
__global__ void zero_kernel() {
    int t = threadIdx.x;
    g_binCnt[t] = 0;
}

__global__ void __launch_bounds__(256)
hist_kernel(const float4* __restrict__ xyuv,
            const float* __restrict__ mn4, const float* __restrict__ mx4, int n) {
    __shared__ unsigned int h[NBINS];
    for (int b = threadIdx.x; b < NBINS; b += blockDim.x) h[b] = 0;
    __syncthreads();
    int i = blockIdx.x * blockDim.x + threadIdx.x;
    if (i < n) atomicAdd(&h[compute_bin(xyuv[i], mn4, mx4)], 1u);
    __syncthreads();
    for (int b = threadIdx.x; b < NBINS; b += blockDim.x)
        if (h[b]) atomicAdd(&g_binCnt[b], h[b]);
}

__global__ void scan_kernel() {
    __shared__ unsigned int s[NBINS];
    int t = threadIdx.x;
    s[t] = g_binCnt[t];
    __syncthreads();
    for (int off = 1; off < NBINS; off <<= 1) {
        unsigned int v = (t >= off) ? s[t - off] : 0u;
        __syncthreads();
        s[t] += v;
        __syncthreads();
    }
    g_binCursor[t] = (t == 0) ? 0u : s[t - 1];   // exclusive prefix
}

__global__ void __launch_bounds__(256)
scatter_kernel(const float4* __restrict__ xyuv,
               const float* __restrict__ mn4, const float* __restrict__ mx4, int n) {
    int i = blockIdx.x * blockDim.x + threadIdx.x;
    if (i >= n) return;
    int bin = compute_bin(xyuv[i], mn4, mx4);
    unsigned int pos = atomicAdd(&g_binCursor[bin], 1u);
    g_binIdx[pos] = (unsigned int)i;
}

// ---------------- phase 3: gather ----------------
__global__ void __launch_bounds__(256)
gather_kernel(const float4* __restrict__ xyuv,
              const float* __restrict__ mn4,
              const float* __restrict__ mx4,
              float* __restrict__ out, int n) {
    int t = blockIdx.x * blockDim.x + threadIdx.x;
    if (t >= n) return;
    int i = (int)g_binIdx[t];

    float4 c = xyuv[i];

    int x0, y0, u0, v0, dx, dy, du, dv;
    float wx0, wx1, wy0, wy1, wu0, wu1, wv0, wv1;
    prep_dim(c.x, mn4[0], mx4[0], XX, x0, dx, wx0, wx1);
    prep_dim(c.y, mn4[1], mx4[1], YY, y0, dy, wy0, wy1);
    prep_dim(c.z, mn4[2], mx4[2], UU, u0, du, wu0, wu1);
    prep_dim(c.w, mn4[3], mx4[3], VV, v0, dv, wv0, wv1);

    int sidx[8];
    float w[8];
#pragma unroll
    for (int k = 0; k < 8; k++) {
        int xa = (k >> 2) & 1;
        int ya = (k >> 1) & 1;
        int ua = k & 1;
        int xi = x0 + (xa ? dx : 0);
        int yi = y0 + (ya ? dy : 0);
        int ui = u0 + (ua ? du : 0);
        sidx[k] = ((xi * YY + yi) * UU + ui) * VV + v0;
        w[k] = (xa ? wx1 : wx0) * (ya ? wy1 : wy0) * (ua ? wu1 : wu0);
    }

    float acc[RR];
#pragma unroll
    for (int r = 0; r < RR; r++) acc[r] = 0.0f;

#pragma unroll 2
    for (int k = 0; k < 8; k++) {
        int s0 = sidx[k];
        uint4 A = g_gridT[s0];
        uint4 B = g_gridT[s0 + dv];
        float wa = w[k] * wv0;
        float wb = w[k] * wv1;
        const unsigned int* au = &A.x;
        const unsigned int* bu = &B.x;
#pragma unroll
        for (int p = 0; p < 4; p++) {
            float2 fa = __half22float2(u32_to_h2(au[p]));
            float2 fb = __half22float2(u32_to_h2(bu[p]));
            acc[2 * p + 0] = fmaf(wa, fa.x, fmaf(wb, fb.x, acc[2 * p + 0]));
            acc[2 * p + 1] = fmaf(wa, fa.y, fmaf(wb, fb.y, acc[2 * p + 1]));
        }
    }

    float4* o4 = reinterpret_cast<float4*>(out + (size_t)i * RR);
    o4[0] = make_float4(acc[0], acc[1], acc[2], acc[3]);
    o4[1] = make_float4(acc[4], acc[5], acc[6], acc[7]);
}

extern "C" void kernel_launch(void* const* d_in, const int* in_sizes, int n_in,
                              void* d_out, int out_size) {
    const float4* xyuv = (const float4*)d_in[0];
    const float* grid  = (const float*)d_in[1];
    const float* mn4   = (const float*)d_in[2];
    const float* mx4   = (const float*)d_in[3];
    float* out = (float*)d_out;

    int n = in_sizes[0] / 4;  // 1,048,576 points
    if (n > NCAP) n = NCAP;

    int tThreads = 256;
    int tBlocks = (NS + tThreads - 1) / tThreads;
    transpose_kernel<<<tBlocks, tThreads>>>(grid);

    int pBlocks = (n + 255) / 256;
    zero_kernel<<<1, NBINS>>>();
    hist_kernel<<<pBlocks, 256>>>(xyuv, mn4, mx4, n);
    scan_kernel<<<1, NBINS>>>();
    scatter_kernel<<<pBlocks, 256>>>(xyuv, mn4, mx4, n);

    gather_kernel<<<pBlocks, 256>>>(xyuv, mn4, mx4, out, n);
}

// round 6
// speedup vs baseline: 1.0239x; 1.0239x over previous
#include <cuda_runtime.h>
#include <cuda_fp16.h>

// Grid4D quadrilinear sample:
//  1) transpose grid [R,X,Y,U,V] fp32 -> gridT [X,Y,U,V,R] fp16 (16B/cell)
//  2) bin points by (x0,y0,u0>>6) -> 512 bins; write compacted coord records
//  3) persistent gather with ticket queue: concurrent frontier ~45MB < L2

#define RR 8
#define XX 9
#define YY 9
#define UU 512
#define VV 512
#define NS (XX * YY * UU * VV)     // 21,233,664 spatial cells
#define STR_R (NS)

#define NBINS 512
#define NCAP (1 << 20)
#define GATHER_BLOCKS 592          // 4 per SM
#define CHUNK 256

__device__ uint4 g_gridT[(size_t)NS];            // ~340 MB fp16 transposed grid
__device__ unsigned int g_binCnt[NBINS];
__device__ unsigned int g_binCursor[NBINS];
__device__ float4 g_pts[NCAP];                   // sorted coords (16 MB)
__device__ unsigned int g_oidx[NCAP];            // original index (4 MB)
__device__ unsigned int g_ticket;

__device__ __forceinline__ unsigned int h2_to_u32(__half2 v) {
    return *reinterpret_cast<unsigned int*>(&v);
}
__device__ __forceinline__ __half2 u32_to_h2(unsigned int v) {
    return *reinterpret_cast<__half2*>(&v);
}

// ---------------- phase 1: transpose ----------------
__global__ void __launch_bounds__(256)
transpose_kernel(const float* __restrict__ grid) {
    int s = blockIdx.x * blockDim.x + threadIdx.x;
    if (s >= NS) return;
    uint4 packed;
    unsigned int* pu = &packed.x;
#pragma unroll
    for (int p = 0; p < 4; p++) {
        float a = __ldg(grid + (2 * p + 0) * STR_R + s);
        float b = __ldg(grid + (2 * p + 1) * STR_R + s);
        pu[p] = h2_to_u32(__floats2half2_rn(a, b));
    }
    g_gridT[s] = packed;
}

// ---------------- shared coordinate math ----------------
__device__ __forceinline__ void prep_dim(float c, float mn, float mx, int S,
                                         int& c0, int& dd, float& w0, float& w1) {
    float ind = (c - mn) / (mx - mn) * 2.0f - 1.0f;
    float pos = (ind + 1.0f) * 0.5f * (float)(S - 1);
    float fl = floorf(pos);
    int i0 = (int)fl;
    float f = pos - fl;
    w0 = 1.0f - f;
    w1 = f;
    if (i0 < 0 || i0 >= S) w0 = 0.0f;        // zero-padding semantics
    int i1 = i0 + 1;
    if (i1 < 0 || i1 >= S) w1 = 0.0f;
    int cc0 = min(max(i0, 0), S - 1);
    int cc1 = min(max(i1, 0), S - 1);
    c0 = cc0;
    dd = cc1 - cc0;                           // 0 or 1
}

__device__ __forceinline__ int base_idx(float c, float mn, float mx, int S) {
    float ind = (c - mn) / (mx - mn) * 2.0f - 1.0f;
    float pos = (ind + 1.0f) * 0.5f * (float)(S - 1);
    int i0 = (int)floorf(pos);
    return min(max(i0, 0), S - 1);
}

__device__ __forceinline__ int compute_bin(float4 c, const float* mn4, const float* mx4) {
    int x0 = base_idx(c.x, mn4[0], mx4[0], XX);
    int y0 = base_idx(c.y, mn4[1], mx4[1], YY);
    int u0 = base_idx(c.z, mn4[2], mx4[2], UU);
    return (min(x0, 7) << 6) | (min(y0, 7) << 3) | (u0 >> 6);
}

// ---------------- phase 2: binning ----------------
__global__ void zero_kernel() {
    int t = threadIdx.x;
    g_binCnt[t] = 0;
    if (t == 0) g_ticket = 0;
}

__global__ void __launch_bounds__(256)
hist_kernel(const float4* __restrict__ xyuv,
            const float* __restrict__ mn4, const float* __restrict__ mx4, int n) {
    __shared__ unsigned int h[NBINS];
    for (int b = threadIdx.x; b < NBINS; b += blockDim.x) h[b] = 0;
    __syncthreads();
    int i = blockIdx.x * blockDim.x + threadIdx.x;
    if (i < n) atomicAdd(&h[compute_bin(xyuv[i], mn4, mx4)], 1u);
    __syncthreads();
    for (int b = threadIdx.x; b < NBINS; b += blockDim.x)
        if (h[b]) atomicAdd(&g_binCnt[b], h[b]);
}

__global__ void scan_kernel() {
    __shared__ unsigned int s[NBINS];
    int t = threadIdx.x;
    s[t] = g_binCnt[t];
    __syncthreads();
    for (int off = 1; off < NBINS; off <<= 1) {
        unsigned int v = (t >= off) ? s[t - off] : 0u;
        __syncthreads();
        s[t] += v;
        __syncthreads();
    }
    g_binCursor[t] = (t == 0) ? 0u : s[t - 1];   // exclusive prefix
}

__global__ void __launch_bounds__(256)
scatter_kernel(const float4* __restrict__ xyuv,
               const float* __restrict__ mn4, const float* __restrict__ mx4, int n) {
    int i = blockIdx.x * blockDim.x + threadIdx.x;
    if (i >= n) return;
    float4 c = xyuv[i];
    int bin = compute_bin(c, mn4, mx4);
    unsigned int pos = atomicAdd(&g_binCursor[bin], 1u);
    g_pts[pos] = c;
    g_oidx[pos] = (unsigned int)i;
}

// ---------------- phase 3: persistent gather with ticket queue ----------------
__global__ void __launch_bounds__(256)
gather_kernel(const float* __restrict__ mn4,
              const float* __restrict__ mx4,
              float* __restrict__ out, int n) {
    __shared__ unsigned int s_chunk;
    int nChunks = (n + CHUNK - 1) / CHUNK;

    for (;;) {
        if (threadIdx.x == 0) s_chunk = atomicAdd(&g_ticket, 1u);
        __syncthreads();
        unsigned int chunk = s_chunk;
        __syncthreads();
        if (chunk >= (unsigned int)nChunks) return;

        int t = (int)chunk * CHUNK + threadIdx.x;
        if (t < n) {
            float4 c = g_pts[t];

            int x0, y0, u0, v0, dx, dy, du, dv;
            float wx0, wx1, wy0, wy1, wu0, wu1, wv0, wv1;
            prep_dim(c.x, mn4[0], mx4[0], XX, x0, dx, wx0, wx1);
            prep_dim(c.y, mn4[1], mx4[1], YY, y0, dy, wy0, wy1);
            prep_dim(c.z, mn4[2], mx4[2], UU, u0, du, wu0, wu1);
            prep_dim(c.w, mn4[3], mx4[3], VV, v0, dv, wv0, wv1);

            int sidx[8];
            float w[8];
#pragma unroll
            for (int k = 0; k < 8; k++) {
                int xa = (k >> 2) & 1;
                int ya = (k >> 1) & 1;
                int ua = k & 1;
                int xi = x0 + (xa ? dx : 0);
                int yi = y0 + (ya ? dy : 0);
                int ui = u0 + (ua ? du : 0);
                sidx[k] = ((xi * YY + yi) * UU + ui) * VV + v0;
                w[k] = (xa ? wx1 : wx0) * (ya ? wy1 : wy0) * (ua ? wu1 : wu0);
            }

            float acc[RR];
#pragma unroll
            for (int r = 0; r < RR; r++) acc[r] = 0.0f;

#pragma unroll 2
            for (int k = 0; k < 8; k++) {
                int s0 = sidx[k];
                uint4 A = g_gridT[s0];
                uint4 B = g_gridT[s0 + dv];
                float wa = w[k] * wv0;
                float wb = w[k] * wv1;
                const unsigned int* au = &A.x;
                const unsigned int* bu = &B.x;
#pragma unroll
                for (int p = 0; p < 4; p++) {
                    float2 fa = __half22float2(u32_to_h2(au[p]));
                    float2 fb = __half22float2(u32_to_h2(bu[p]));
                    acc[2 * p + 0] = fmaf(wa, fa.x, fmaf(wb, fb.x, acc[2 * p + 0]));
                    acc[2 * p + 1] = fmaf(wa, fa.y, fmaf(wb, fb.y, acc[2 * p + 1]));
                }
            }

            unsigned int oi = g_oidx[t];
            float4* o4 = reinterpret_cast<float4*>(out + (size_t)oi * RR);
            o4[0] = make_float4(acc[0], acc[1], acc[2], acc[3]);
            o4[1] = make_float4(acc[4], acc[5], acc[6], acc[7]);
        }
    }
}

extern "C" void kernel_launch(void* const* d_in, const int* in_sizes, int n_in,
                              void* d_out, int out_size) {
    const float4* xyuv = (const float4*)d_in[0];
    const float* grid  = (const float*)d_in[1];
    const float* mn4   = (const float*)d_in[2];
    const float* mx4   = (const float*)d_in[3];
    float* out = (float*)d_out;

    int n = in_sizes[0] / 4;  // 1,048,576 points
    if (n > NCAP) n = NCAP;

    int tThreads = 256;
    int tBlocks = (NS + tThreads - 1) / tThreads;
    transpose_kernel<<<tBlocks, tThreads>>>(grid);

    int pBlocks = (n + 255) / 256;
    zero_kernel<<<1, NBINS>>>();
    hist_kernel<<<pBlocks, 256>>>(xyuv, mn4, mx4, n);
    scan_kernel<<<1, NBINS>>>();
    scatter_kernel<<<pBlocks, 256>>>(xyuv, mn4, mx4, n);

    gather_kernel<<<GATHER_BLOCKS, 256>>>(mn4, mx4, out, n);
}

// round 7
// speedup vs baseline: 1.4363x; 1.4027x over previous
#include <cuda_runtime.h>
#include <cuda_fp16.h>

// Grid4D quadrilinear sample:
//  1) transpose grid [R,X,Y,U,V] fp32 -> gridT [X,Y,U,V,R] fp16 (16B/cell)
//  2) bin points by (Morton(u_hi3,v_hi3), x0, y0) -> 4096 bins (v now in key!)
//  3) persistent gather in bin order: frontier line-footprint ~55MB < L2

#define RR 8
#define XX 9
#define YY 9
#define UU 512
#define VV 512
#define NS (XX * YY * UU * VV)     // 21,233,664 spatial cells
#define STR_R (NS)

#define NBINS 4096
#define NCAP (1 << 20)
#define GATHER_BLOCKS 592          // 4 per SM
#define CHUNK 256

__device__ uint4 g_gridT[(size_t)NS];            // ~340 MB fp16 transposed grid
__device__ unsigned int g_binCnt[NBINS];
__device__ unsigned int g_binCursor[NBINS];
__device__ float4 g_pts[NCAP];                   // sorted coords (16 MB)
__device__ unsigned int g_oidx[NCAP];            // original index (4 MB)
__device__ unsigned int g_ticket;

__device__ __forceinline__ unsigned int h2_to_u32(__half2 v) {
    return *reinterpret_cast<unsigned int*>(&v);
}
__device__ __forceinline__ __half2 u32_to_h2(unsigned int v) {
    return *reinterpret_cast<__half2*>(&v);
}

// ---------------- phase 1: transpose ----------------
__global__ void __launch_bounds__(256)
transpose_kernel(const float* __restrict__ grid) {
    int s = blockIdx.x * blockDim.x + threadIdx.x;
    if (s >= NS) return;
    uint4 packed;
    unsigned int* pu = &packed.x;
#pragma unroll
    for (int p = 0; p < 4; p++) {
        float a = __ldg(grid + (2 * p + 0) * STR_R + s);
        float b = __ldg(grid + (2 * p + 1) * STR_R + s);
        pu[p] = h2_to_u32(__floats2half2_rn(a, b));
    }
    g_gridT[s] = packed;
}

// ---------------- shared coordinate math ----------------
__device__ __forceinline__ void prep_dim(float c, float mn, float mx, int S,
                                         int& c0, int& dd, float& w0, float& w1) {
    float ind = (c - mn) / (mx - mn) * 2.0f - 1.0f;
    float pos = (ind + 1.0f) * 0.5f * (float)(S - 1);
    float fl = floorf(pos);
    int i0 = (int)fl;
    float f = pos - fl;
    w0 = 1.0f - f;
    w1 = f;
    if (i0 < 0 || i0 >= S) w0 = 0.0f;        // zero-padding semantics
    int i1 = i0 + 1;
    if (i1 < 0 || i1 >= S) w1 = 0.0f;
    int cc0 = min(max(i0, 0), S - 1);
    int cc1 = min(max(i1, 0), S - 1);
    c0 = cc0;
    dd = cc1 - cc0;                           // 0 or 1
}

__device__ __forceinline__ int base_idx(float c, float mn, float mx, int S) {
    float ind = (c - mn) / (mx - mn) * 2.0f - 1.0f;
    float pos = (ind + 1.0f) * 0.5f * (float)(S - 1);
    int i0 = (int)floorf(pos);
    return min(max(i0, 0), S - 1);
}

__device__ __forceinline__ int morton3(int a, int b) {  // a,b in [0,8) -> 6 bits
    return ((a & 1) << 0) | ((b & 1) << 1) |
           (((a >> 1) & 1) << 2) | (((b >> 1) & 1) << 3) |
           (((a >> 2) & 1) << 4) | (((b >> 2) & 1) << 5);
}

__device__ __forceinline__ int compute_bin(float4 c, const float* mn4, const float* mx4) {
    int x0 = min(base_idx(c.x, mn4[0], mx4[0], XX), 7);
    int y0 = min(base_idx(c.y, mn4[1], mx4[1], YY), 7);
    int u0 = base_idx(c.z, mn4[2], mx4[2], UU);
    int v0 = base_idx(c.w, mn4[3], mx4[3], VV);
    return (morton3(u0 >> 6, v0 >> 6) << 6) | (x0 << 3) | y0;
}

// ---------------- phase 2: binning ----------------
__global__ void zero_kernel() {
    int b = blockIdx.x * blockDim.x + threadIdx.x;
    if (b < NBINS) g_binCnt[b] = 0;
    if (b == 0) g_ticket = 0;
}

__global__ void __launch_bounds__(256)
hist_kernel(const float4* __restrict__ xyuv,
            const float* __restrict__ mn4, const float* __restrict__ mx4, int n) {
    __shared__ unsigned int h[NBINS];
    for (int b = threadIdx.x; b < NBINS; b += blockDim.x) h[b] = 0;
    __syncthreads();
    int i = blockIdx.x * blockDim.x + threadIdx.x;
    if (i < n) atomicAdd(&h[compute_bin(xyuv[i], mn4, mx4)], 1u);
    __syncthreads();
    for (int b = threadIdx.x; b < NBINS; b += blockDim.x)
        if (h[b]) atomicAdd(&g_binCnt[b], h[b]);
}

__global__ void __launch_bounds__(1024)
scan_kernel() {   // 1 block, 1024 threads, 4 bins each
    __shared__ unsigned int part[1024];
    int t = threadIdx.x;
    unsigned int v0 = g_binCnt[t * 4 + 0];
    unsigned int v1 = g_binCnt[t * 4 + 1];
    unsigned int v2 = g_binCnt[t * 4 + 2];
    unsigned int v3 = g_binCnt[t * 4 + 3];
    part[t] = v0 + v1 + v2 + v3;
    __syncthreads();
    for (int off = 1; off < 1024; off <<= 1) {
        unsigned int x = (t >= off) ? part[t - off] : 0u;
        __syncthreads();
        part[t] += x;
        __syncthreads();
    }
    unsigned int base = (t == 0) ? 0u : part[t - 1];
    g_binCursor[t * 4 + 0] = base;
    g_binCursor[t * 4 + 1] = base + v0;
    g_binCursor[t * 4 + 2] = base + v0 + v1;
    g_binCursor[t * 4 + 3] = base + v0 + v1 + v2;
}

__global__ void __launch_bounds__(256)
scatter_kernel(const float4* __restrict__ xyuv,
               const float* __restrict__ mn4, const float* __restrict__ mx4, int n) {
    int i = blockIdx.x * blockDim.x + threadIdx.x;
    if (i >= n) return;
    float4 c = xyuv[i];
    int bin = compute_bin(c, mn4, mx4);
    unsigned int pos = atomicAdd(&g_binCursor[bin], 1u);
    g_pts[pos] = c;
    g_oidx[pos] = (unsigned int)i;
}

// ---------------- phase 3: persistent gather with ticket queue ----------------
__global__ void __launch_bounds__(256)
gather_kernel(const float* __restrict__ mn4,
              const float* __restrict__ mx4,
              float* __restrict__ out, int n) {
    __shared__ unsigned int s_chunk;
    int nChunks = (n + CHUNK - 1) / CHUNK;

    for (;;) {
        __syncthreads();
        if (threadIdx.x == 0) s_chunk = atomicAdd(&g_ticket, 1u);
        __syncthreads();
        unsigned int chunk = s_chunk;
        if (chunk >= (unsigned int)nChunks) return;

        int t = (int)chunk * CHUNK + threadIdx.x;
        if (t < n) {
            float4 c = g_pts[t];

            int x0, y0, u0, v0, dx, dy, du, dv;
            float wx0, wx1, wy0, wy1, wu0, wu1, wv0, wv1;
            prep_dim(c.x, mn4[0], mx4[0], XX, x0, dx, wx0, wx1);
            prep_dim(c.y, mn4[1], mx4[1], YY, y0, dy, wy0, wy1);
            prep_dim(c.z, mn4[2], mx4[2], UU, u0, du, wu0, wu1);
            prep_dim(c.w, mn4[3], mx4[3], VV, v0, dv, wv0, wv1);

            int sidx[8];
            float w[8];
#pragma unroll
            for (int k = 0; k < 8; k++) {
                int xa = (k >> 2) & 1;
                int ya = (k >> 1) & 1;
                int ua = k & 1;
                int xi = x0 + (xa ? dx : 0);
                int yi = y0 + (ya ? dy : 0);
                int ui = u0 + (ua ? du : 0);
                sidx[k] = ((xi * YY + yi) * UU + ui) * VV + v0;
                w[k] = (xa ? wx1 : wx0) * (ya ? wy1 : wy0) * (ua ? wu1 : wu0);
            }

            float acc[RR];
#pragma unroll
            for (int r = 0; r < RR; r++) acc[r] = 0.0f;

#pragma unroll 2
            for (int k = 0; k < 8; k++) {
                int s0 = sidx[k];
                uint4 A = g_gridT[s0];
                uint4 B = g_gridT[s0 + dv];
                float wa = w[k] * wv0;
                float wb = w[k] * wv1;
                const unsigned int* au = &A.x;
                const unsigned int* bu = &B.x;
#pragma unroll
                for (int p = 0; p < 4; p++) {
                    float2 fa = __half22float2(u32_to_h2(au[p]));
                    float2 fb = __half22float2(u32_to_h2(bu[p]));
                    acc[2 * p + 0] = fmaf(wa, fa.x, fmaf(wb, fb.x, acc[2 * p + 0]));
                    acc[2 * p + 1] = fmaf(wa, fa.y, fmaf(wb, fb.y, acc[2 * p + 1]));
                }
            }

            unsigned int oi = g_oidx[t];
            float4* o4 = reinterpret_cast<float4*>(out + (size_t)oi * RR);
            o4[0] = make_float4(acc[0], acc[1], acc[2], acc[3]);
            o4[1] = make_float4(acc[4], acc[5], acc[6], acc[7]);
        }
    }
}

extern "C" void kernel_launch(void* const* d_in, const int* in_sizes, int n_in,
                              void* d_out, int out_size) {
    const float4* xyuv = (const float4*)d_in[0];
    const float* grid  = (const float*)d_in[1];
    const float* mn4   = (const float*)d_in[2];
    const float* mx4   = (const float*)d_in[3];
    float* out = (float*)d_out;

    int n = in_sizes[0] / 4;  // 1,048,576 points
    if (n > NCAP) n = NCAP;

    int tThreads = 256;
    int tBlocks = (NS + tThreads - 1) / tThreads;
    transpose_kernel<<<tBlocks, tThreads>>>(grid);

    int pBlocks = (n + 255) / 256;
    zero_kernel<<<(NBINS + 1023) / 1024, 1024>>>();
    hist_kernel<<<pBlocks, 256>>>(xyuv, mn4, mx4, n);
    scan_kernel<<<1, 1024>>>();
    scatter_kernel<<<pBlocks, 256>>>(xyuv, mn4, mx4, n);

    gather_kernel<<<GATHER_BLOCKS, 256>>>(mn4, mx4, out, n);
}